// round 10
// baseline (speedup 1.0000x reference)
#include <cuda_runtime.h>
#include <cuda_fp16.h>
#include <cstdint>

#define NROWS 8192
#define DIN   256
#define DOUT  128
#define KC    64
#define TILE_M 128
#define NCTA  296
#define SLOTS 6

// ---- device-global scratch (no allocations allowed; zero-initialized) ----
__device__ __half g_h[(size_t)NROWS * DOUT];   // h fp16 row-major
__device__ float  g_B[NROWS];
__device__ float  g_D[NROWS];
__device__ float  g_E[NROWS];
__device__ float  g_acc[SLOTS][(size_t)NROWS * DOUT];  // slot partials (zero-init)
__device__ float  g_rs[SLOTS][NROWS];                  // rowsum partials (zero-init)

__device__ __forceinline__ uint32_t smem_u32(const void* p) {
    uint32_t a;
    asm("{ .reg .u64 t; cvta.to.shared.u64 t, %1; cvt.u32.u64 %0, t; }" : "=r"(a) : "l"(p));
    return a;
}

#define CP_ASYNC16(dst, src) \
    asm volatile("cp.async.cg.shared.global [%0], [%1], 16;" :: "r"(dst), "l"(src) : "memory")
#define CP_COMMIT() asm volatile("cp.async.commit_group;" ::: "memory")
#define CP_WAIT0()  asm volatile("cp.async.wait_group 0;" ::: "memory")

// ============ K1: h = xW + b -> g_h fp16, plus B/D/E vectors ============
// 512 CTAs x 256 threads, 16 rows/CTA. Warp w owns rows w*2, w*2+1.
// Thread: 2 rows x 4 cols register block (2x the warps of R9 for latency hiding).
#define K1_ROWS 16
#define XS_STR  20
#define WS_STR  132

__global__ __launch_bounds__(256) void k1_linear(
    const float* __restrict__ x, const float* __restrict__ W,
    const float* __restrict__ bW, const float* __restrict__ a1,
    const float* __restrict__ a2, const float* __restrict__ ba_p)
{
    __shared__ float xs[64 * XS_STR];
    __shared__ float ws[64 * WS_STR];

    const int tid  = threadIdx.x;
    const int wid  = tid >> 5;       // 0..7
    const int lane = tid & 31;
    const int rb = blockIdx.x * K1_ROWS;
    const int r0 = wid * 2;
    const int c0 = lane * 4;

    float acc[2][4];
    #pragma unroll
    for (int i = 0; i < 2; i++)
        #pragma unroll
        for (int j = 0; j < 4; j++) acc[i][j] = 0.f;

    for (int kc = 0; kc < DIN; kc += 64) {
        __syncthreads();
        // x tile transposed: 16 rows x 64 k = 256 float4, one per thread
        {
            int r = tid >> 4, q = tid & 15;
            float4 v = __ldg((const float4*)&x[(size_t)(rb + r) * DIN + kc + q * 4]);
            xs[(q * 4 + 0) * XS_STR + r] = v.x;
            xs[(q * 4 + 1) * XS_STR + r] = v.y;
            xs[(q * 4 + 2) * XS_STR + r] = v.z;
            xs[(q * 4 + 3) * XS_STR + r] = v.w;
        }
        // W tile: 64 k x 32 float4 = 2048, 8 per thread
        #pragma unroll
        for (int e = tid; e < 2048; e += 256) {
            int k = e >> 5, cq = e & 31;
            *(float4*)&ws[k * WS_STR + cq * 4] =
                __ldg((const float4*)&W[(size_t)(kc + k) * DOUT + cq * 4]);
        }
        __syncthreads();

        #pragma unroll 16
        for (int k = 0; k < 64; k++) {
            float2 xr = *(const float2*)&xs[k * XS_STR + r0];
            float4 wc = *(const float4*)&ws[k * WS_STR + c0];
            acc[0][0] += xr.x * wc.x; acc[0][1] += xr.x * wc.y;
            acc[0][2] += xr.x * wc.z; acc[0][3] += xr.x * wc.w;
            acc[1][0] += xr.y * wc.x; acc[1][1] += xr.y * wc.y;
            acc[1][2] += xr.y * wc.z; acc[1][3] += xr.y * wc.w;
        }
    }

    float bv[4];
    *(float4*)bv = __ldg((const float4*)&bW[c0]);
    #pragma unroll
    for (int i = 0; i < 2; i++)
        #pragma unroll
        for (int j = 0; j < 4; j++) acc[i][j] += bv[j];

    #pragma unroll
    for (int i = 0; i < 2; i++) {
        __half2 p0 = __floats2half2_rn(acc[i][0], acc[i][1]);
        __half2 p1 = __floats2half2_rn(acc[i][2], acc[i][3]);
        uint2 v = make_uint2(*(const uint32_t*)&p0, *(const uint32_t*)&p1);
        *(uint2*)(g_h + (size_t)(rb + r0 + i) * DOUT + c0) = v;
    }

    float a1v[4], a2v[4];
    *(float4*)a1v = __ldg((const float4*)&a1[c0]);
    *(float4*)a2v = __ldg((const float4*)&a2[c0]);
    float s1p[2], s2p[2];
    #pragma unroll
    for (int i = 0; i < 2; i++) {
        s1p[i] = acc[i][0]*a1v[0] + acc[i][1]*a1v[1] + acc[i][2]*a1v[2] + acc[i][3]*a1v[3];
        s2p[i] = acc[i][0]*a2v[0] + acc[i][1]*a2v[1] + acc[i][2]*a2v[2] + acc[i][3]*a2v[3];
    }
    #pragma unroll
    for (int m = 16; m >= 1; m >>= 1) {
        #pragma unroll
        for (int i = 0; i < 2; i++) {
            s1p[i] += __shfl_xor_sync(0xffffffffu, s1p[i], m);
            s2p[i] += __shfl_xor_sync(0xffffffffu, s2p[i], m);
        }
    }
    if (lane == 0) {
        const float bav = ba_p[0];
        #pragma unroll
        for (int i = 0; i < 2; i++) {
            int row = rb + r0 + i;
            float u = s1p[i] + bav;
            g_E[row] = expf(-0.99f * u);
            g_B[row] = expf(s2p[i]);
            g_D[row] = expf(0.01f * s2p[i]);
        }
    }
}

// ============ K2: fused masked-softmax-numerator GEMM ============
// 296 CTAs, balanced flattened ranges, double-buffered smem,
// adj reg-prefetch + cp.async h across MMA, fp32-accum HMMA,
// warp tile 32x64, P'-produce interleaved into the MMA ss-loop.
#define PSTR 72u
#define HSTR 136u
#define PBUF (128u * PSTR * 2u)   // 18432 B
#define HBUF (64u * HSTR * 2u)    // 17408 B
#define SMEM_K2 (2 * 18432 + 2 * 17408)  // 71680 B

__global__ __launch_bounds__(256, 2) void k2_fused(const int* __restrict__ adj)
{
    extern __shared__ char smem[];
    const uint32_t sPb = smem_u32(smem);
    const uint32_t sHb = sPb + 2u * PBUF;

    const int tid  = threadIdx.x;
    const int wid  = tid >> 5;
    const int lane = tid & 31;
    const int cta  = blockIdx.x;
    const int slot = cta % SLOTS;

    // balanced flattened chunk range: [s, e) out of 64*128 = 8192 chunk-units
    const int s = (1024 * cta) / 37;          // = cta*8192/296
    const int e = (1024 * (cta + 1)) / 37;

    // P'/adj mapping: thread owns rows tr+32k (k=0..3), j's jq8*8..+8
    const int tr  = tid >> 3;      // 0..31
    const int jq8 = tid & 7;       // 0..7

    // h cp.async mapping: thread copies 64B of j-row hjr
    const int hjr = tid >> 2;            // 0..63
    const int hcb = (tid & 3) * 64;      // byte offset in 256B row

    // warp tile: mwarp in 0..3 (32-row stripe), nwarp in 0..1 (64-col half)
    const int mwarp = wid & 3;
    const int nwarp = wid >> 2;
    const uint32_t ncol0 = (uint32_t)nwarp * 64u;

    // ldmatrix lane addressing (half units)
    const int g  = lane >> 3;
    const int l7 = lane & 7;
    const uint32_t aRow0 = (uint32_t)(mwarp * 32 + (g & 1) * 8 + l7) * PSTR + (uint32_t)((g >> 1) * 8);
    const uint32_t aRow1 = aRow0 + 16u * PSTR;
    const uint32_t bBase = (uint32_t)((g & 1) * 8 + l7) * HSTR + (uint32_t)((g >> 1) * 8) + ncol0;

    const uint32_t sPst = ((uint32_t)tr * PSTR + (uint32_t)jq8 * 8u) * 2u;
    const uint32_t sHst = (uint32_t)hjr * HSTR * 2u + (uint32_t)hcb;

    const float* Bp = g_B + jq8 * 8;
    const float* Dp = g_D + jq8 * 8;

    const int t0 = s >> 7, t1 = (e - 1) >> 7;
    for (int t = t0; t <= t1; ++t) {
        const int c0 = (s > (t << 7)) ? s : (t << 7);
        const int c1 = (e < ((t + 1) << 7)) ? e : ((t + 1) << 7);
        const int rowb = t * TILE_M;

        float Ei[4];
        #pragma unroll
        for (int k = 0; k < 4; k++) Ei[k] = g_E[rowb + tr + 32 * k];

        const int* adjbase = adj + (size_t)(rowb + tr) * NROWS + jq8 * 8;

        // facc[mt*8 + nt*2 + hh][4]
        float facc[16][4];
        #pragma unroll
        for (int n = 0; n < 16; n++)
            #pragma unroll
            for (int c = 0; c < 4; c++) facc[n][c] = 0.f;
        float rsum[4] = {0.f, 0.f, 0.f, 0.f};

        int4 adjr[8];
        float4 B0r, B1r, D0r, D1r;

        // one k-step of P' production (uses adjr[2k],adjr[2k+1], B/D regs)
        auto produce_k = [&](int k, uint32_t stb) {
            int4 a0 = adjr[2 * k], a1 = adjr[2 * k + 1];
            float v0 = fmaxf(B0r.x, Ei[k] * D0r.x); v0 = a0.x ? v0 : 0.f;
            float v1 = fmaxf(B0r.y, Ei[k] * D0r.y); v1 = a0.y ? v1 : 0.f;
            float v2 = fmaxf(B0r.z, Ei[k] * D0r.z); v2 = a0.z ? v2 : 0.f;
            float v3 = fmaxf(B0r.w, Ei[k] * D0r.w); v3 = a0.w ? v3 : 0.f;
            float v4 = fmaxf(B1r.x, Ei[k] * D1r.x); v4 = a1.x ? v4 : 0.f;
            float v5 = fmaxf(B1r.y, Ei[k] * D1r.y); v5 = a1.y ? v5 : 0.f;
            float v6 = fmaxf(B1r.z, Ei[k] * D1r.z); v6 = a1.z ? v6 : 0.f;
            float v7 = fmaxf(B1r.w, Ei[k] * D1r.w); v7 = a1.w ? v7 : 0.f;
            rsum[k] += ((v0 + v1) + (v2 + v3)) + ((v4 + v5) + (v6 + v7));
            __half2 p0 = __floats2half2_rn(v0, v1);
            __half2 p1 = __floats2half2_rn(v2, v3);
            __half2 p2 = __floats2half2_rn(v4, v5);
            __half2 p3 = __floats2half2_rn(v6, v7);
            asm volatile("st.shared.v4.b32 [%0], {%1,%2,%3,%4};"
                :: "r"(stb + (uint32_t)(32 * k) * PSTR * 2u),
                   "r"(*(const uint32_t*)&p0), "r"(*(const uint32_t*)&p1),
                   "r"(*(const uint32_t*)&p2), "r"(*(const uint32_t*)&p3) : "memory");
        };

        // ---- prologue: stage chunk c0 into buffer 0 ----
        {
            const int jb = (c0 & 127) * KC;
            #pragma unroll
            for (int k = 0; k < 4; k++) {
                const int4* p = (const int4*)(adjbase + (size_t)(32 * k) * NROWS + jb);
                adjr[2 * k]     = __ldg(p);
                adjr[2 * k + 1] = __ldg(p + 1);
            }
            const char* hsrc = (const char*)g_h + ((size_t)(jb + hjr) * DOUT) * 2 + hcb;
            #pragma unroll
            for (int q = 0; q < 4; q++)
                CP_ASYNC16(sHb + sHst + (uint32_t)q * 16u, hsrc + q * 16);
            CP_COMMIT();
            B0r = __ldg((const float4*)(Bp + jb));
            B1r = __ldg((const float4*)(Bp + jb + 4));
            D0r = __ldg((const float4*)(Dp + jb));
            D1r = __ldg((const float4*)(Dp + jb + 4));
            CP_WAIT0();
            #pragma unroll
            for (int k = 0; k < 4; k++) produce_k(k, sPb + sPst);
        }
        __syncthreads();

        for (int cc = c0; cc < c1; ++cc) {
            const int b = (cc - c0) & 1;
            const uint32_t Pcur = sPb + (uint32_t)b * PBUF;
            const uint32_t Hcur = sHb + (uint32_t)b * HBUF;
            const uint32_t Pnxt = sPb + (uint32_t)(b ^ 1) * PBUF;
            const uint32_t Hnxt = sHb + (uint32_t)(b ^ 1) * HBUF;
            const bool more = (cc + 1 < c1);
            const int jbn = ((cc + 1) & 127) * KC;

            if (more) {
                #pragma unroll
                for (int k = 0; k < 4; k++) {
                    const int4* p = (const int4*)(adjbase + (size_t)(32 * k) * NROWS + jbn);
                    adjr[2 * k]     = __ldg(p);
                    adjr[2 * k + 1] = __ldg(p + 1);
                }
                const char* hsrc = (const char*)g_h + ((size_t)(jbn + hjr) * DOUT) * 2 + hcb;
                #pragma unroll
                for (int q = 0; q < 4; q++)
                    CP_ASYNC16(Hnxt + sHst + (uint32_t)q * 16u, hsrc + q * 16);
                CP_COMMIT();
                B0r = __ldg((const float4*)(Bp + jbn));
                B1r = __ldg((const float4*)(Bp + jbn + 4));
                D0r = __ldg((const float4*)(Dp + jbn));
                D1r = __ldg((const float4*)(Dp + jbn + 4));
            }

            // ---- HMMA fp32-accum, warp tile 32x64; produce interleaved per ss ----
            #pragma unroll
            for (int ss = 0; ss < 4; ++ss) {
                uint32_t A0[4], A1[4];
                asm volatile("ldmatrix.sync.aligned.m8n8.x4.shared.b16 {%0,%1,%2,%3}, [%4];"
                    : "=r"(A0[0]), "=r"(A0[1]), "=r"(A0[2]), "=r"(A0[3])
                    : "r"(Pcur + (aRow0 + (uint32_t)ss * 16u) * 2u));
                asm volatile("ldmatrix.sync.aligned.m8n8.x4.shared.b16 {%0,%1,%2,%3}, [%4];"
                    : "=r"(A1[0]), "=r"(A1[1]), "=r"(A1[2]), "=r"(A1[3])
                    : "r"(Pcur + (aRow1 + (uint32_t)ss * 16u) * 2u));
                #pragma unroll
                for (int nt = 0; nt < 4; ++nt) {
                    uint32_t b0, b1, b2, b3;
                    asm volatile("ldmatrix.sync.aligned.m8n8.x4.trans.shared.b16 {%0,%1,%2,%3}, [%4];"
                        : "=r"(b0), "=r"(b1), "=r"(b2), "=r"(b3)
                        : "r"(Hcur + (bBase + (uint32_t)ss * 16u * HSTR + (uint32_t)nt * 16u) * 2u));
                    float* d00 = facc[nt * 2];
                    float* d01 = facc[nt * 2 + 1];
                    float* d10 = facc[8 + nt * 2];
                    float* d11 = facc[8 + nt * 2 + 1];
                    asm volatile("mma.sync.aligned.m16n8k16.row.col.f32.f16.f16.f32 "
                        "{%0,%1,%2,%3}, {%4,%5,%6,%7}, {%8,%9}, {%0,%1,%2,%3};"
                        : "+f"(d00[0]), "+f"(d00[1]), "+f"(d00[2]), "+f"(d00[3])
                        : "r"(A0[0]), "r"(A0[1]), "r"(A0[2]), "r"(A0[3]), "r"(b0), "r"(b1));
                    asm volatile("mma.sync.aligned.m16n8k16.row.col.f32.f16.f16.f32 "
                        "{%0,%1,%2,%3}, {%4,%5,%6,%7}, {%8,%9}, {%0,%1,%2,%3};"
                        : "+f"(d01[0]), "+f"(d01[1]), "+f"(d01[2]), "+f"(d01[3])
                        : "r"(A0[0]), "r"(A0[1]), "r"(A0[2]), "r"(A0[3]), "r"(b2), "r"(b3));
                    asm volatile("mma.sync.aligned.m16n8k16.row.col.f32.f16.f16.f32 "
                        "{%0,%1,%2,%3}, {%4,%5,%6,%7}, {%8,%9}, {%0,%1,%2,%3};"
                        : "+f"(d10[0]), "+f"(d10[1]), "+f"(d10[2]), "+f"(d10[3])
                        : "r"(A1[0]), "r"(A1[1]), "r"(A1[2]), "r"(A1[3]), "r"(b0), "r"(b1));
                    asm volatile("mma.sync.aligned.m16n8k16.row.col.f32.f16.f16.f32 "
                        "{%0,%1,%2,%3}, {%4,%5,%6,%7}, {%8,%9}, {%0,%1,%2,%3};"
                        : "+f"(d11[0]), "+f"(d11[1]), "+f"(d11[2]), "+f"(d11[3])
                        : "r"(A1[0]), "r"(A1[1]), "r"(A1[2]), "r"(A1[3]), "r"(b2), "r"(b3));
                }
                if (more) produce_k(ss, Pnxt + sPst);
            }

            CP_WAIT0();
            __syncthreads();
        }

        // ---- flush partials for this tile into slot buffers ----
        {
            const int r  = lane >> 2;
            const int c2 = (lane & 3) * 2;
            #pragma unroll
            for (int mt = 0; mt < 2; ++mt) {
                const int row0 = rowb + mwarp * 32 + mt * 16 + r;
                float* dst0 = &g_acc[slot][(size_t)row0 * DOUT];
                float* dst1 = dst0 + (size_t)8 * DOUT;
                #pragma unroll
                for (int nt = 0; nt < 4; ++nt) {
                    #pragma unroll
                    for (int hh = 0; hh < 2; ++hh) {
                        const float* f = facc[mt * 8 + nt * 2 + hh];
                        int col = nwarp * 64 + nt * 16 + hh * 8 + c2;
                        *(float2*)(dst0 + col) = make_float2(f[0], f[1]);
                        *(float2*)(dst1 + col) = make_float2(f[2], f[3]);
                    }
                }
            }
        }
        #pragma unroll
        for (int m = 1; m <= 4; m <<= 1) {
            #pragma unroll
            for (int k = 0; k < 4; k++)
                rsum[k] += __shfl_xor_sync(0xffffffffu, rsum[k], m);
        }
        if (jq8 == 0) {
            #pragma unroll
            for (int k = 0; k < 4; k++)
                g_rs[slot][rowb + tr + 32 * k] = rsum[k];
        }
        __syncthreads();   // smem reuse safety across segments
    }
}

// ============ K3: sum slot partials, normalize ============
__global__ __launch_bounds__(256) void k3_final(float* __restrict__ out)
{
    const int idx = blockIdx.x * 256 + threadIdx.x;   // float4 index
    const int row = idx >> 5;                         // 32 float4 per row
    float rs = 0.f;
    #pragma unroll
    for (int s2 = 0; s2 < SLOTS; s2++) rs += g_rs[s2][row];
    const float inv = 1.0f / rs;
    float ox = 0.f, oy = 0.f, oz = 0.f, ow = 0.f;
    #pragma unroll
    for (int s2 = 0; s2 < SLOTS; s2++) {
        float4 a = ((const float4*)g_acc[s2])[idx];
        ox += a.x; oy += a.y; oz += a.z; ow += a.w;
    }
    float4 o;
    o.x = ox * inv; o.y = oy * inv; o.z = oz * inv; o.w = ow * inv;
    ((float4*)out)[idx] = o;
}

extern "C" void kernel_launch(void* const* d_in, const int* in_sizes, int n_in,
                              void* d_out, int out_size) {
    const float* x   = (const float*)d_in[0];
    const int*   adj = (const int*)  d_in[1];
    const float* W   = (const float*)d_in[2];
    const float* bW  = (const float*)d_in[3];
    const float* a1  = (const float*)d_in[4];
    const float* a2  = (const float*)d_in[5];
    const float* ba  = (const float*)d_in[6];
    float* out = (float*)d_out;

    static bool attr_set = false;
    if (!attr_set) {
        cudaFuncSetAttribute(k2_fused, cudaFuncAttributeMaxDynamicSharedMemorySize, SMEM_K2);
        attr_set = true;
    }

    k1_linear<<<NROWS / K1_ROWS, 256>>>(x, W, bW, a1, a2, ba);
    k2_fused<<<NCTA, 256, SMEM_K2>>>(adj);
    k3_final<<<(NROWS * DOUT / 4) / 256, 256>>>(out);
}

// round 11
// speedup vs baseline: 1.0696x; 1.0696x over previous
#include <cuda_runtime.h>
#include <cuda_fp16.h>
#include <cstdint>

#define NROWS 8192
#define DIN   256
#define DOUT  128
#define KC    64
#define TILE_M 128
#define NCTA  296
#define SLOTS 6

// ---- device-global scratch (no allocations allowed; zero-initialized) ----
__device__ __half g_h[(size_t)NROWS * DOUT];   // h fp16 row-major
__device__ float  g_B[NROWS];
__device__ float  g_D[NROWS];
__device__ float  g_E[NROWS];
__device__ float  g_acc[SLOTS][(size_t)NROWS * DOUT];  // slot partials (zero-init)
__device__ float  g_rs[SLOTS][NROWS];                  // rowsum partials (zero-init)

__device__ __forceinline__ uint32_t smem_u32(const void* p) {
    uint32_t a;
    asm("{ .reg .u64 t; cvta.to.shared.u64 t, %1; cvt.u32.u64 %0, t; }" : "=r"(a) : "l"(p));
    return a;
}

#define CP_ASYNC16(dst, src) \
    asm volatile("cp.async.cg.shared.global [%0], [%1], 16;" :: "r"(dst), "l"(src) : "memory")
#define CP_COMMIT() asm volatile("cp.async.commit_group;" ::: "memory")
#define CP_WAIT0()  asm volatile("cp.async.wait_group 0;" ::: "memory")

// ============ K1: h = xW + b -> g_h fp16, plus B/D/E vectors ============
// 512 CTAs x 128 threads, 16 rows/CTA. Warp w owns rows w*4..w*4+3.
// Thread: 4 rows x 4 cols register block (R9 configuration — best measured).
#define K1_ROWS 16
#define XS_STR  20
#define WS_STR  132

__global__ __launch_bounds__(128) void k1_linear(
    const float* __restrict__ x, const float* __restrict__ W,
    const float* __restrict__ bW, const float* __restrict__ a1,
    const float* __restrict__ a2, const float* __restrict__ ba_p)
{
    __shared__ float xs[64 * XS_STR];
    __shared__ float ws[64 * WS_STR];

    const int tid  = threadIdx.x;
    const int wid  = tid >> 5;
    const int lane = tid & 31;
    const int rb = blockIdx.x * K1_ROWS;
    const int r0 = wid * 4;
    const int c0 = lane * 4;

    float acc[4][4];
    #pragma unroll
    for (int i = 0; i < 4; i++)
        #pragma unroll
        for (int j = 0; j < 4; j++) acc[i][j] = 0.f;

    for (int kc = 0; kc < DIN; kc += 64) {
        __syncthreads();
        #pragma unroll
        for (int e = tid; e < 256; e += 128) {
            int r = e >> 4, q = e & 15;
            float4 v = __ldg((const float4*)&x[(size_t)(rb + r) * DIN + kc + q * 4]);
            xs[(q * 4 + 0) * XS_STR + r] = v.x;
            xs[(q * 4 + 1) * XS_STR + r] = v.y;
            xs[(q * 4 + 2) * XS_STR + r] = v.z;
            xs[(q * 4 + 3) * XS_STR + r] = v.w;
        }
        #pragma unroll
        for (int e = tid; e < 2048; e += 128) {
            int k = e >> 5, cq = e & 31;
            *(float4*)&ws[k * WS_STR + cq * 4] =
                __ldg((const float4*)&W[(size_t)(kc + k) * DOUT + cq * 4]);
        }
        __syncthreads();

        #pragma unroll 8
        for (int k = 0; k < 64; k++) {
            float xr[4], wc[4];
            *(float4*)xr = *(const float4*)&xs[k * XS_STR + r0];
            *(float4*)wc = *(const float4*)&ws[k * WS_STR + c0];
            #pragma unroll
            for (int i = 0; i < 4; i++)
                #pragma unroll
                for (int j = 0; j < 4; j++)
                    acc[i][j] += xr[i] * wc[j];
        }
    }

    float bv[4];
    *(float4*)bv = __ldg((const float4*)&bW[c0]);
    #pragma unroll
    for (int i = 0; i < 4; i++)
        #pragma unroll
        for (int j = 0; j < 4; j++) acc[i][j] += bv[j];

    #pragma unroll
    for (int i = 0; i < 4; i++) {
        __half2 p0 = __floats2half2_rn(acc[i][0], acc[i][1]);
        __half2 p1 = __floats2half2_rn(acc[i][2], acc[i][3]);
        uint2 v = make_uint2(*(const uint32_t*)&p0, *(const uint32_t*)&p1);
        *(uint2*)(g_h + (size_t)(rb + r0 + i) * DOUT + c0) = v;
    }

    float a1v[4], a2v[4];
    *(float4*)a1v = __ldg((const float4*)&a1[c0]);
    *(float4*)a2v = __ldg((const float4*)&a2[c0]);
    float s1p[4], s2p[4];
    #pragma unroll
    for (int i = 0; i < 4; i++) {
        s1p[i] = acc[i][0]*a1v[0] + acc[i][1]*a1v[1] + acc[i][2]*a1v[2] + acc[i][3]*a1v[3];
        s2p[i] = acc[i][0]*a2v[0] + acc[i][1]*a2v[1] + acc[i][2]*a2v[2] + acc[i][3]*a2v[3];
    }
    #pragma unroll
    for (int m = 16; m >= 1; m >>= 1) {
        #pragma unroll
        for (int i = 0; i < 4; i++) {
            s1p[i] += __shfl_xor_sync(0xffffffffu, s1p[i], m);
            s2p[i] += __shfl_xor_sync(0xffffffffu, s2p[i], m);
        }
    }
    if (lane == 0) {
        const float bav = ba_p[0];
        #pragma unroll
        for (int i = 0; i < 4; i++) {
            int row = rb + r0 + i;
            float u = s1p[i] + bav;
            g_E[row] = expf(-0.99f * u);
            g_B[row] = expf(s2p[i]);
            g_D[row] = expf(0.01f * s2p[i]);
        }
    }
}

// ============ K2: fused masked-softmax-numerator GEMM ============
// 296 CTAs, balanced flattened ranges, double-buffered smem,
// adj reg-prefetch + cp.async h across MMA, fp32-accum HMMA,
// warp tile 32x64, P'-produce interleaved into the MMA ss-loop.
#define PSTR 72u
#define HSTR 136u
#define PBUF (128u * PSTR * 2u)   // 18432 B
#define HBUF (64u * HSTR * 2u)    // 17408 B
#define SMEM_K2 (2 * 18432 + 2 * 17408)  // 71680 B

__global__ __launch_bounds__(256, 2) void k2_fused(const int* __restrict__ adj)
{
    extern __shared__ char smem[];
    const uint32_t sPb = smem_u32(smem);
    const uint32_t sHb = sPb + 2u * PBUF;

    const int tid  = threadIdx.x;
    const int wid  = tid >> 5;
    const int lane = tid & 31;
    const int cta  = blockIdx.x;
    const int slot = cta % SLOTS;

    // balanced flattened chunk range: [s, e) out of 64*128 = 8192 chunk-units
    const int s = (1024 * cta) / 37;          // = cta*8192/296
    const int e = (1024 * (cta + 1)) / 37;

    // P'/adj mapping: thread owns rows tr+32k (k=0..3), j's jq8*8..+8
    const int tr  = tid >> 3;      // 0..31
    const int jq8 = tid & 7;       // 0..7

    // h cp.async mapping: thread copies 64B of j-row hjr
    const int hjr = tid >> 2;            // 0..63
    const int hcb = (tid & 3) * 64;      // byte offset in 256B row

    // warp tile: mwarp in 0..3 (32-row stripe), nwarp in 0..1 (64-col half)
    const int mwarp = wid & 3;
    const int nwarp = wid >> 2;
    const uint32_t ncol0 = (uint32_t)nwarp * 64u;

    // ldmatrix lane addressing (half units)
    const int g  = lane >> 3;
    const int l7 = lane & 7;
    const uint32_t aRow0 = (uint32_t)(mwarp * 32 + (g & 1) * 8 + l7) * PSTR + (uint32_t)((g >> 1) * 8);
    const uint32_t aRow1 = aRow0 + 16u * PSTR;
    const uint32_t bBase = (uint32_t)((g & 1) * 8 + l7) * HSTR + (uint32_t)((g >> 1) * 8) + ncol0;

    const uint32_t sPst = ((uint32_t)tr * PSTR + (uint32_t)jq8 * 8u) * 2u;
    const uint32_t sHst = (uint32_t)hjr * HSTR * 2u + (uint32_t)hcb;

    const float* Bp = g_B + jq8 * 8;
    const float* Dp = g_D + jq8 * 8;

    const int t0 = s >> 7, t1 = (e - 1) >> 7;
    for (int t = t0; t <= t1; ++t) {
        const int c0 = (s > (t << 7)) ? s : (t << 7);
        const int c1 = (e < ((t + 1) << 7)) ? e : ((t + 1) << 7);
        const int rowb = t * TILE_M;

        float Ei[4];
        #pragma unroll
        for (int k = 0; k < 4; k++) Ei[k] = g_E[rowb + tr + 32 * k];

        const int* adjbase = adj + (size_t)(rowb + tr) * NROWS + jq8 * 8;

        // facc[mt*8 + nt*2 + hh][4]
        float facc[16][4];
        #pragma unroll
        for (int n = 0; n < 16; n++)
            #pragma unroll
            for (int c = 0; c < 4; c++) facc[n][c] = 0.f;
        float rsum[4] = {0.f, 0.f, 0.f, 0.f};

        int4 adjr[8];
        float4 B0r, B1r, D0r, D1r;

        // one k-step of P' production (uses adjr[2k],adjr[2k+1], B/D regs)
        auto produce_k = [&](int k, uint32_t stb) {
            int4 a0 = adjr[2 * k], a1 = adjr[2 * k + 1];
            float v0 = fmaxf(B0r.x, Ei[k] * D0r.x); v0 = a0.x ? v0 : 0.f;
            float v1 = fmaxf(B0r.y, Ei[k] * D0r.y); v1 = a0.y ? v1 : 0.f;
            float v2 = fmaxf(B0r.z, Ei[k] * D0r.z); v2 = a0.z ? v2 : 0.f;
            float v3 = fmaxf(B0r.w, Ei[k] * D0r.w); v3 = a0.w ? v3 : 0.f;
            float v4 = fmaxf(B1r.x, Ei[k] * D1r.x); v4 = a1.x ? v4 : 0.f;
            float v5 = fmaxf(B1r.y, Ei[k] * D1r.y); v5 = a1.y ? v5 : 0.f;
            float v6 = fmaxf(B1r.z, Ei[k] * D1r.z); v6 = a1.z ? v6 : 0.f;
            float v7 = fmaxf(B1r.w, Ei[k] * D1r.w); v7 = a1.w ? v7 : 0.f;
            rsum[k] += ((v0 + v1) + (v2 + v3)) + ((v4 + v5) + (v6 + v7));
            __half2 p0 = __floats2half2_rn(v0, v1);
            __half2 p1 = __floats2half2_rn(v2, v3);
            __half2 p2 = __floats2half2_rn(v4, v5);
            __half2 p3 = __floats2half2_rn(v6, v7);
            asm volatile("st.shared.v4.b32 [%0], {%1,%2,%3,%4};"
                :: "r"(stb + (uint32_t)(32 * k) * PSTR * 2u),
                   "r"(*(const uint32_t*)&p0), "r"(*(const uint32_t*)&p1),
                   "r"(*(const uint32_t*)&p2), "r"(*(const uint32_t*)&p3) : "memory");
        };

        // ---- prologue: stage chunk c0 into buffer 0 ----
        {
            const int jb = (c0 & 127) * KC;
            #pragma unroll
            for (int k = 0; k < 4; k++) {
                const int4* p = (const int4*)(adjbase + (size_t)(32 * k) * NROWS + jb);
                adjr[2 * k]     = __ldg(p);
                adjr[2 * k + 1] = __ldg(p + 1);
            }
            const char* hsrc = (const char*)g_h + ((size_t)(jb + hjr) * DOUT) * 2 + hcb;
            #pragma unroll
            for (int q = 0; q < 4; q++)
                CP_ASYNC16(sHb + sHst + (uint32_t)q * 16u, hsrc + q * 16);
            CP_COMMIT();
            B0r = __ldg((const float4*)(Bp + jb));
            B1r = __ldg((const float4*)(Bp + jb + 4));
            D0r = __ldg((const float4*)(Dp + jb));
            D1r = __ldg((const float4*)(Dp + jb + 4));
            CP_WAIT0();
            #pragma unroll
            for (int k = 0; k < 4; k++) produce_k(k, sPb + sPst);
        }
        __syncthreads();

        for (int cc = c0; cc < c1; ++cc) {
            const int b = (cc - c0) & 1;
            const uint32_t Pcur = sPb + (uint32_t)b * PBUF;
            const uint32_t Hcur = sHb + (uint32_t)b * HBUF;
            const uint32_t Pnxt = sPb + (uint32_t)(b ^ 1) * PBUF;
            const uint32_t Hnxt = sHb + (uint32_t)(b ^ 1) * HBUF;
            const bool more = (cc + 1 < c1);
            const int jbn = ((cc + 1) & 127) * KC;

            if (more) {
                #pragma unroll
                for (int k = 0; k < 4; k++) {
                    const int4* p = (const int4*)(adjbase + (size_t)(32 * k) * NROWS + jbn);
                    adjr[2 * k]     = __ldg(p);
                    adjr[2 * k + 1] = __ldg(p + 1);
                }
                const char* hsrc = (const char*)g_h + ((size_t)(jbn + hjr) * DOUT) * 2 + hcb;
                #pragma unroll
                for (int q = 0; q < 4; q++)
                    CP_ASYNC16(Hnxt + sHst + (uint32_t)q * 16u, hsrc + q * 16);
                CP_COMMIT();
                B0r = __ldg((const float4*)(Bp + jbn));
                B1r = __ldg((const float4*)(Bp + jbn + 4));
                D0r = __ldg((const float4*)(Dp + jbn));
                D1r = __ldg((const float4*)(Dp + jbn + 4));
            }

            // ---- HMMA fp32-accum, warp tile 32x64; produce interleaved per ss ----
            #pragma unroll
            for (int ss = 0; ss < 4; ++ss) {
                uint32_t A0[4], A1[4];
                asm volatile("ldmatrix.sync.aligned.m8n8.x4.shared.b16 {%0,%1,%2,%3}, [%4];"
                    : "=r"(A0[0]), "=r"(A0[1]), "=r"(A0[2]), "=r"(A0[3])
                    : "r"(Pcur + (aRow0 + (uint32_t)ss * 16u) * 2u));
                asm volatile("ldmatrix.sync.aligned.m8n8.x4.shared.b16 {%0,%1,%2,%3}, [%4];"
                    : "=r"(A1[0]), "=r"(A1[1]), "=r"(A1[2]), "=r"(A1[3])
                    : "r"(Pcur + (aRow1 + (uint32_t)ss * 16u) * 2u));
                #pragma unroll
                for (int nt = 0; nt < 4; ++nt) {
                    uint32_t b0, b1, b2, b3;
                    asm volatile("ldmatrix.sync.aligned.m8n8.x4.trans.shared.b16 {%0,%1,%2,%3}, [%4];"
                        : "=r"(b0), "=r"(b1), "=r"(b2), "=r"(b3)
                        : "r"(Hcur + (bBase + (uint32_t)ss * 16u * HSTR + (uint32_t)nt * 16u) * 2u));
                    float* d00 = facc[nt * 2];
                    float* d01 = facc[nt * 2 + 1];
                    float* d10 = facc[8 + nt * 2];
                    float* d11 = facc[8 + nt * 2 + 1];
                    asm volatile("mma.sync.aligned.m16n8k16.row.col.f32.f16.f16.f32 "
                        "{%0,%1,%2,%3}, {%4,%5,%6,%7}, {%8,%9}, {%0,%1,%2,%3};"
                        : "+f"(d00[0]), "+f"(d00[1]), "+f"(d00[2]), "+f"(d00[3])
                        : "r"(A0[0]), "r"(A0[1]), "r"(A0[2]), "r"(A0[3]), "r"(b0), "r"(b1));
                    asm volatile("mma.sync.aligned.m16n8k16.row.col.f32.f16.f16.f32 "
                        "{%0,%1,%2,%3}, {%4,%5,%6,%7}, {%8,%9}, {%0,%1,%2,%3};"
                        : "+f"(d01[0]), "+f"(d01[1]), "+f"(d01[2]), "+f"(d01[3])
                        : "r"(A0[0]), "r"(A0[1]), "r"(A0[2]), "r"(A0[3]), "r"(b2), "r"(b3));
                    asm volatile("mma.sync.aligned.m16n8k16.row.col.f32.f16.f16.f32 "
                        "{%0,%1,%2,%3}, {%4,%5,%6,%7}, {%8,%9}, {%0,%1,%2,%3};"
                        : "+f"(d10[0]), "+f"(d10[1]), "+f"(d10[2]), "+f"(d10[3])
                        : "r"(A1[0]), "r"(A1[1]), "r"(A1[2]), "r"(A1[3]), "r"(b0), "r"(b1));
                    asm volatile("mma.sync.aligned.m16n8k16.row.col.f32.f16.f16.f32 "
                        "{%0,%1,%2,%3}, {%4,%5,%6,%7}, {%8,%9}, {%0,%1,%2,%3};"
                        : "+f"(d11[0]), "+f"(d11[1]), "+f"(d11[2]), "+f"(d11[3])
                        : "r"(A1[0]), "r"(A1[1]), "r"(A1[2]), "r"(A1[3]), "r"(b2), "r"(b3));
                }
                if (more) produce_k(ss, Pnxt + sPst);
            }

            CP_WAIT0();
            __syncthreads();
        }

        // ---- flush partials for this tile into slot buffers ----
        {
            const int r  = lane >> 2;
            const int c2 = (lane & 3) * 2;
            #pragma unroll
            for (int mt = 0; mt < 2; ++mt) {
                const int row0 = rowb + mwarp * 32 + mt * 16 + r;
                float* dst0 = &g_acc[slot][(size_t)row0 * DOUT];
                float* dst1 = dst0 + (size_t)8 * DOUT;
                #pragma unroll
                for (int nt = 0; nt < 4; ++nt) {
                    #pragma unroll
                    for (int hh = 0; hh < 2; ++hh) {
                        const float* f = facc[mt * 8 + nt * 2 + hh];
                        int col = nwarp * 64 + nt * 16 + hh * 8 + c2;
                        *(float2*)(dst0 + col) = make_float2(f[0], f[1]);
                        *(float2*)(dst1 + col) = make_float2(f[2], f[3]);
                    }
                }
            }
        }
        #pragma unroll
        for (int m = 1; m <= 4; m <<= 1) {
            #pragma unroll
            for (int k = 0; k < 4; k++)
                rsum[k] += __shfl_xor_sync(0xffffffffu, rsum[k], m);
        }
        if (jq8 == 0) {
            #pragma unroll
            for (int k = 0; k < 4; k++)
                g_rs[slot][rowb + tr + 32 * k] = rsum[k];
        }
        __syncthreads();   // smem reuse safety across segments
    }
}

// ============ K3: sum slot partials, normalize ============
__global__ __launch_bounds__(256) void k3_final(float* __restrict__ out)
{
    const int idx = blockIdx.x * 256 + threadIdx.x;   // float4 index
    const int row = idx >> 5;                         // 32 float4 per row
    float rs = 0.f;
    #pragma unroll
    for (int s2 = 0; s2 < SLOTS; s2++) rs += g_rs[s2][row];
    const float inv = 1.0f / rs;
    float ox = 0.f, oy = 0.f, oz = 0.f, ow = 0.f;
    #pragma unroll
    for (int s2 = 0; s2 < SLOTS; s2++) {
        float4 a = ((const float4*)g_acc[s2])[idx];
        ox += a.x; oy += a.y; oz += a.z; ow += a.w;
    }
    float4 o;
    o.x = ox * inv; o.y = oy * inv; o.z = oz * inv; o.w = ow * inv;
    ((float4*)out)[idx] = o;
}

extern "C" void kernel_launch(void* const* d_in, const int* in_sizes, int n_in,
                              void* d_out, int out_size) {
    const float* x   = (const float*)d_in[0];
    const int*   adj = (const int*)  d_in[1];
    const float* W   = (const float*)d_in[2];
    const float* bW  = (const float*)d_in[3];
    const float* a1  = (const float*)d_in[4];
    const float* a2  = (const float*)d_in[5];
    const float* ba  = (const float*)d_in[6];
    float* out = (float*)d_out;

    static bool attr_set = false;
    if (!attr_set) {
        cudaFuncSetAttribute(k2_fused, cudaFuncAttributeMaxDynamicSharedMemorySize, SMEM_K2);
        attr_set = true;
    }

    k1_linear<<<NROWS / K1_ROWS, 128>>>(x, W, bW, a1, a2, ba);
    k2_fused<<<NCTA, 256, SMEM_K2>>>(adj);
    k3_final<<<(NROWS * DOUT / 4) / 256, 256>>>(out);
}

// round 12
// speedup vs baseline: 1.1559x; 1.0807x over previous
#include <cuda_runtime.h>
#include <cuda_fp16.h>
#include <cstdint>

#define NROWS 8192
#define DIN   256
#define DOUT  128
#define KC    64
#define TILE_M 128
#define NCTA  296
#define SLOTS 6

// ---- device-global scratch (no allocations allowed; zero-initialized) ----
__device__ __half g_h[(size_t)NROWS * DOUT];   // h fp16 row-major
__device__ __half g_xh[(size_t)NROWS * DIN];   // x hi fp16
__device__ __half g_xl[(size_t)NROWS * DIN];   // x lo fp16
__device__ __half g_Wh[(size_t)DIN * DOUT];
__device__ __half g_Wl[(size_t)DIN * DOUT];
__device__ float  g_B[NROWS];
__device__ float  g_D[NROWS];
__device__ float  g_E[NROWS];
__device__ float  g_acc[SLOTS][(size_t)NROWS * DOUT];  // slot partials (zero-init)
__device__ float  g_rs[SLOTS][NROWS];                  // rowsum partials (zero-init)

__device__ __forceinline__ uint32_t smem_u32(const void* p) {
    uint32_t a;
    asm("{ .reg .u64 t; cvta.to.shared.u64 t, %1; cvt.u32.u64 %0, t; }" : "=r"(a) : "l"(p));
    return a;
}

#define CP_ASYNC16(dst, src) \
    asm volatile("cp.async.cg.shared.global [%0], [%1], 16;" :: "r"(dst), "l"(src) : "memory")
#define CP_COMMIT() asm volatile("cp.async.commit_group;" ::: "memory")
#define CP_WAIT0()  asm volatile("cp.async.wait_group 0;" ::: "memory")
#define CP_WAIT1()  asm volatile("cp.async.wait_group 1;" ::: "memory")

// ============ K0: split x, W into fp16 hi/lo ============
__global__ __launch_bounds__(256) void k0_split(
    const float* __restrict__ x, const float* __restrict__ W)
{
    const int b = blockIdx.x;
    if (b < 1024) {
        size_t e = ((size_t)b * 256 + threadIdx.x) * 8;
        float4 v0 = __ldg((const float4*)(x + e));
        float4 v1 = __ldg((const float4*)(x + e + 4));
        __half hi[8], lo[8];
        const float* v = (const float*)&v0;
        #pragma unroll
        for (int i = 0; i < 4; i++) {
            hi[i] = __float2half_rn(v[i]);
            lo[i] = __float2half_rn(v[i] - __half2float(hi[i]));
        }
        v = (const float*)&v1;
        #pragma unroll
        for (int i = 0; i < 4; i++) {
            hi[4 + i] = __float2half_rn(v[i]);
            lo[4 + i] = __float2half_rn(v[i] - __half2float(hi[4 + i]));
        }
        *(uint4*)(g_xh + e) = *(const uint4*)hi;
        *(uint4*)(g_xl + e) = *(const uint4*)lo;
    } else {
        size_t e = (((size_t)(b - 1024)) * 256 + threadIdx.x) * 8;  // 16 CTAs x 2048 = 32768
        float4 v0 = __ldg((const float4*)(W + e));
        float4 v1 = __ldg((const float4*)(W + e + 4));
        __half hi[8], lo[8];
        const float* v = (const float*)&v0;
        #pragma unroll
        for (int i = 0; i < 4; i++) {
            hi[i] = __float2half_rn(v[i]);
            lo[i] = __float2half_rn(v[i] - __half2float(hi[i]));
        }
        v = (const float*)&v1;
        #pragma unroll
        for (int i = 0; i < 4; i++) {
            hi[4 + i] = __float2half_rn(v[i]);
            lo[4 + i] = __float2half_rn(v[i] - __half2float(hi[4 + i]));
        }
        *(uint4*)(g_Wh + e) = *(const uint4*)hi;
        *(uint4*)(g_Wl + e) = *(const uint4*)lo;
    }
}

// ============ K1: h = xW + b via split-fp16 HMMA, plus B/D/E ============
// 256 CTAs x 256 thr, 32 rows/CTA, K=256 in 4 chunks of 64, double-buffered.
// Warp tile 16m x 32n: mwarp = wid&1, nwarp = wid>>1.
// smem per buffer: Ah[32x72h] Al[32x72h] Bh[64x136h] Bl[64x136h]
#define K1ASTR 72u
#define K1BSTR 136u
#define K1_AH  0u
#define K1_AL  4608u
#define K1_BH  9216u
#define K1_BL  26624u
#define K1BUF  44032u
#define SMEM_K1 (2 * 44032)

__global__ __launch_bounds__(256, 2) void k1_mma(
    const float* __restrict__ bW, const float* __restrict__ a1,
    const float* __restrict__ a2, const float* __restrict__ ba_p)
{
    extern __shared__ char smem[];
    const uint32_t sb = smem_u32(smem);
    __shared__ float red1[32][4];
    __shared__ float red2[32][4];

    const int tid  = threadIdx.x;
    const int wid  = tid >> 5;
    const int lane = tid & 31;
    const int rb   = blockIdx.x * 32;
    const int mwarp = wid & 1;
    const int nwarp = wid >> 1;

    // cp.async mappings
    const int arow = tid >> 3;            // 0..31
    const int apc  = tid & 7;             // 16B piece in 128B row
    const uint32_t aDst = (uint32_t)arow * (K1ASTR * 2u) + (uint32_t)apc * 16u;
    // B: 1024 pieces per array, 4 per thread

    // ldmatrix addressing
    const int g  = lane >> 3;
    const int l7 = lane & 7;
    const uint32_t aOff = (uint32_t)(mwarp * 16 + (g & 1) * 8 + l7) * K1ASTR + (uint32_t)((g >> 1) * 8);
    const uint32_t bOff = (uint32_t)((g & 1) * 8 + l7) * K1BSTR + (uint32_t)((g >> 1) * 8) + (uint32_t)nwarp * 32u;

    float facc[4][4];
    #pragma unroll
    for (int n = 0; n < 4; n++)
        #pragma unroll
        for (int c = 0; c < 4; c++) facc[n][c] = 0.f;

    auto stage = [&](int buf, int chunk) {
        const uint32_t base = sb + (uint32_t)buf * K1BUF;
        const int kc = chunk * 64;
        // A tiles (1 piece each)
        CP_ASYNC16(base + K1_AH + aDst, g_xh + (size_t)(rb + arow) * DIN + kc + apc * 8);
        CP_ASYNC16(base + K1_AL + aDst, g_xl + (size_t)(rb + arow) * DIN + kc + apc * 8);
        // B tiles (4 pieces each)
        #pragma unroll
        for (int i = 0; i < 4; i++) {
            int e2 = tid + 256 * i;
            int k = e2 >> 4, p = e2 & 15;
            uint32_t d = (uint32_t)k * (K1BSTR * 2u) + (uint32_t)p * 16u;
            CP_ASYNC16(base + K1_BH + d, g_Wh + (size_t)(kc + k) * DOUT + p * 8);
            CP_ASYNC16(base + K1_BL + d, g_Wl + (size_t)(kc + k) * DOUT + p * 8);
        }
        CP_COMMIT();
    };

    stage(0, 0);
    for (int cc = 0; cc < 4; ++cc) {
        const int buf = cc & 1;
        if (cc < 3) stage(buf ^ 1, cc + 1);
        if (cc < 3) { CP_WAIT1(); } else { CP_WAIT0(); }
        __syncthreads();
        const uint32_t base = sb + (uint32_t)buf * K1BUF;

        #pragma unroll
        for (int ss = 0; ss < 4; ++ss) {
            uint32_t Ah[4], Al[4];
            asm volatile("ldmatrix.sync.aligned.m8n8.x4.shared.b16 {%0,%1,%2,%3}, [%4];"
                : "=r"(Ah[0]), "=r"(Ah[1]), "=r"(Ah[2]), "=r"(Ah[3])
                : "r"(base + K1_AH + (aOff + (uint32_t)ss * 16u) * 2u));
            asm volatile("ldmatrix.sync.aligned.m8n8.x4.shared.b16 {%0,%1,%2,%3}, [%4];"
                : "=r"(Al[0]), "=r"(Al[1]), "=r"(Al[2]), "=r"(Al[3])
                : "r"(base + K1_AL + (aOff + (uint32_t)ss * 16u) * 2u));
            #pragma unroll
            for (int ntg = 0; ntg < 2; ++ntg) {
                uint32_t bh0, bh1, bh2, bh3, bl0, bl1, bl2, bl3;
                uint32_t baddr = (bOff + (uint32_t)ss * 16u * K1BSTR + (uint32_t)ntg * 16u) * 2u;
                asm volatile("ldmatrix.sync.aligned.m8n8.x4.trans.shared.b16 {%0,%1,%2,%3}, [%4];"
                    : "=r"(bh0), "=r"(bh1), "=r"(bh2), "=r"(bh3) : "r"(base + K1_BH + baddr));
                asm volatile("ldmatrix.sync.aligned.m8n8.x4.trans.shared.b16 {%0,%1,%2,%3}, [%4];"
                    : "=r"(bl0), "=r"(bl1), "=r"(bl2), "=r"(bl3) : "r"(base + K1_BL + baddr));
                float* d0 = facc[ntg * 2];
                float* d1 = facc[ntg * 2 + 1];
                // d0 += Ah*bh(0) + Ah*bl(0) + Al*bh(0)
                asm volatile("mma.sync.aligned.m16n8k16.row.col.f32.f16.f16.f32 "
                    "{%0,%1,%2,%3}, {%4,%5,%6,%7}, {%8,%9}, {%0,%1,%2,%3};"
                    : "+f"(d0[0]), "+f"(d0[1]), "+f"(d0[2]), "+f"(d0[3])
                    : "r"(Ah[0]), "r"(Ah[1]), "r"(Ah[2]), "r"(Ah[3]), "r"(bh0), "r"(bh1));
                asm volatile("mma.sync.aligned.m16n8k16.row.col.f32.f16.f16.f32 "
                    "{%0,%1,%2,%3}, {%4,%5,%6,%7}, {%8,%9}, {%0,%1,%2,%3};"
                    : "+f"(d1[0]), "+f"(d1[1]), "+f"(d1[2]), "+f"(d1[3])
                    : "r"(Ah[0]), "r"(Ah[1]), "r"(Ah[2]), "r"(Ah[3]), "r"(bh2), "r"(bh3));
                asm volatile("mma.sync.aligned.m16n8k16.row.col.f32.f16.f16.f32 "
                    "{%0,%1,%2,%3}, {%4,%5,%6,%7}, {%8,%9}, {%0,%1,%2,%3};"
                    : "+f"(d0[0]), "+f"(d0[1]), "+f"(d0[2]), "+f"(d0[3])
                    : "r"(Ah[0]), "r"(Ah[1]), "r"(Ah[2]), "r"(Ah[3]), "r"(bl0), "r"(bl1));
                asm volatile("mma.sync.aligned.m16n8k16.row.col.f32.f16.f16.f32 "
                    "{%0,%1,%2,%3}, {%4,%5,%6,%7}, {%8,%9}, {%0,%1,%2,%3};"
                    : "+f"(d1[0]), "+f"(d1[1]), "+f"(d1[2]), "+f"(d1[3])
                    : "r"(Ah[0]), "r"(Ah[1]), "r"(Ah[2]), "r"(Ah[3]), "r"(bl2), "r"(bl3));
                asm volatile("mma.sync.aligned.m16n8k16.row.col.f32.f16.f16.f32 "
                    "{%0,%1,%2,%3}, {%4,%5,%6,%7}, {%8,%9}, {%0,%1,%2,%3};"
                    : "+f"(d0[0]), "+f"(d0[1]), "+f"(d0[2]), "+f"(d0[3])
                    : "r"(Al[0]), "r"(Al[1]), "r"(Al[2]), "r"(Al[3]), "r"(bh0), "r"(bh1));
                asm volatile("mma.sync.aligned.m16n8k16.row.col.f32.f16.f16.f32 "
                    "{%0,%1,%2,%3}, {%4,%5,%6,%7}, {%8,%9}, {%0,%1,%2,%3};"
                    : "+f"(d1[0]), "+f"(d1[1]), "+f"(d1[2]), "+f"(d1[3])
                    : "r"(Al[0]), "r"(Al[1]), "r"(Al[2]), "r"(Al[3]), "r"(bh2), "r"(bh3));
            }
        }
        __syncthreads();   // MMA reads done before next stage overwrites
    }

    // ---- epilogue: bias, h write, s1/s2, E/B/D ----
    const int r  = lane >> 2;
    const int c2 = (lane & 3) * 2;
    const int row0 = mwarp * 16 + r;        // local rows row0, row0+8
    float s1a = 0.f, s2a = 0.f, s1b = 0.f, s2b = 0.f;

    #pragma unroll
    for (int nt = 0; nt < 4; ++nt) {
        const int col = nwarp * 32 + nt * 8 + c2;
        float2 bv = *(const float2*)&bW[col];
        float2 a1v = *(const float2*)&a1[col];
        float2 a2v = *(const float2*)&a2[col];
        float h00 = facc[nt][0] + bv.x, h01 = facc[nt][1] + bv.y;
        float h10 = facc[nt][2] + bv.x, h11 = facc[nt][3] + bv.y;
        __half2 p0 = __floats2half2_rn(h00, h01);
        __half2 p1 = __floats2half2_rn(h10, h11);
        *(uint32_t*)(g_h + (size_t)(rb + row0) * DOUT + col)     = *(const uint32_t*)&p0;
        *(uint32_t*)(g_h + (size_t)(rb + row0 + 8) * DOUT + col) = *(const uint32_t*)&p1;
        s1a += h00 * a1v.x + h01 * a1v.y;
        s2a += h00 * a2v.x + h01 * a2v.y;
        s1b += h10 * a1v.x + h11 * a1v.y;
        s2b += h10 * a2v.x + h11 * a2v.y;
    }
    // reduce over the 4 lanes sharing a row
    #pragma unroll
    for (int m = 1; m <= 2; m <<= 1) {
        s1a += __shfl_xor_sync(0xffffffffu, s1a, m);
        s2a += __shfl_xor_sync(0xffffffffu, s2a, m);
        s1b += __shfl_xor_sync(0xffffffffu, s1b, m);
        s2b += __shfl_xor_sync(0xffffffffu, s2b, m);
    }
    if ((lane & 3) == 0) {
        red1[row0][nwarp] = s1a;  red2[row0][nwarp] = s2a;
        red1[row0 + 8][nwarp] = s1b;  red2[row0 + 8][nwarp] = s2b;
    }
    __syncthreads();
    if (tid < 32) {
        float s1 = red1[tid][0] + red1[tid][1] + red1[tid][2] + red1[tid][3];
        float s2 = red2[tid][0] + red2[tid][1] + red2[tid][2] + red2[tid][3];
        float u = s1 + ba_p[0];
        g_E[rb + tid] = expf(-0.99f * u);
        g_B[rb + tid] = expf(s2);
        g_D[rb + tid] = expf(0.01f * s2);
    }
}

// ============ K2: fused masked-softmax-numerator GEMM (unchanged R11) ============
#define PSTR 72u
#define HSTR 136u
#define PBUF (128u * PSTR * 2u)
#define HBUF (64u * HSTR * 2u)
#define SMEM_K2 (2 * 18432 + 2 * 17408)

__global__ __launch_bounds__(256, 2) void k2_fused(const int* __restrict__ adj)
{
    extern __shared__ char smem[];
    const uint32_t sPb = smem_u32(smem);
    const uint32_t sHb = sPb + 2u * PBUF;

    const int tid  = threadIdx.x;
    const int wid  = tid >> 5;
    const int lane = tid & 31;
    const int cta  = blockIdx.x;
    const int slot = cta % SLOTS;

    const int s = (1024 * cta) / 37;
    const int e = (1024 * (cta + 1)) / 37;

    const int tr  = tid >> 3;
    const int jq8 = tid & 7;
    const int hjr = tid >> 2;
    const int hcb = (tid & 3) * 64;

    const int mwarp = wid & 3;
    const int nwarp = wid >> 2;
    const uint32_t ncol0 = (uint32_t)nwarp * 64u;

    const int g  = lane >> 3;
    const int l7 = lane & 7;
    const uint32_t aRow0 = (uint32_t)(mwarp * 32 + (g & 1) * 8 + l7) * PSTR + (uint32_t)((g >> 1) * 8);
    const uint32_t aRow1 = aRow0 + 16u * PSTR;
    const uint32_t bBase = (uint32_t)((g & 1) * 8 + l7) * HSTR + (uint32_t)((g >> 1) * 8) + ncol0;

    const uint32_t sPst = ((uint32_t)tr * PSTR + (uint32_t)jq8 * 8u) * 2u;
    const uint32_t sHst = (uint32_t)hjr * HSTR * 2u + (uint32_t)hcb;

    const float* Bp = g_B + jq8 * 8;
    const float* Dp = g_D + jq8 * 8;

    const int t0 = s >> 7, t1 = (e - 1) >> 7;
    for (int t = t0; t <= t1; ++t) {
        const int c0 = (s > (t << 7)) ? s : (t << 7);
        const int c1 = (e < ((t + 1) << 7)) ? e : ((t + 1) << 7);
        const int rowb = t * TILE_M;

        float Ei[4];
        #pragma unroll
        for (int k = 0; k < 4; k++) Ei[k] = g_E[rowb + tr + 32 * k];

        const int* adjbase = adj + (size_t)(rowb + tr) * NROWS + jq8 * 8;

        float facc[16][4];
        #pragma unroll
        for (int n = 0; n < 16; n++)
            #pragma unroll
            for (int c = 0; c < 4; c++) facc[n][c] = 0.f;
        float rsum[4] = {0.f, 0.f, 0.f, 0.f};

        int4 adjr[8];
        float4 B0r, B1r, D0r, D1r;

        auto produce_k = [&](int k, uint32_t stb) {
            int4 a0 = adjr[2 * k], a1 = adjr[2 * k + 1];
            float v0 = fmaxf(B0r.x, Ei[k] * D0r.x); v0 = a0.x ? v0 : 0.f;
            float v1 = fmaxf(B0r.y, Ei[k] * D0r.y); v1 = a0.y ? v1 : 0.f;
            float v2 = fmaxf(B0r.z, Ei[k] * D0r.z); v2 = a0.z ? v2 : 0.f;
            float v3 = fmaxf(B0r.w, Ei[k] * D0r.w); v3 = a0.w ? v3 : 0.f;
            float v4 = fmaxf(B1r.x, Ei[k] * D1r.x); v4 = a1.x ? v4 : 0.f;
            float v5 = fmaxf(B1r.y, Ei[k] * D1r.y); v5 = a1.y ? v5 : 0.f;
            float v6 = fmaxf(B1r.z, Ei[k] * D1r.z); v6 = a1.z ? v6 : 0.f;
            float v7 = fmaxf(B1r.w, Ei[k] * D1r.w); v7 = a1.w ? v7 : 0.f;
            rsum[k] += ((v0 + v1) + (v2 + v3)) + ((v4 + v5) + (v6 + v7));
            __half2 p0 = __floats2half2_rn(v0, v1);
            __half2 p1 = __floats2half2_rn(v2, v3);
            __half2 p2 = __floats2half2_rn(v4, v5);
            __half2 p3 = __floats2half2_rn(v6, v7);
            asm volatile("st.shared.v4.b32 [%0], {%1,%2,%3,%4};"
                :: "r"(stb + (uint32_t)(32 * k) * PSTR * 2u),
                   "r"(*(const uint32_t*)&p0), "r"(*(const uint32_t*)&p1),
                   "r"(*(const uint32_t*)&p2), "r"(*(const uint32_t*)&p3) : "memory");
        };

        {
            const int jb = (c0 & 127) * KC;
            #pragma unroll
            for (int k = 0; k < 4; k++) {
                const int4* p = (const int4*)(adjbase + (size_t)(32 * k) * NROWS + jb);
                adjr[2 * k]     = __ldg(p);
                adjr[2 * k + 1] = __ldg(p + 1);
            }
            const char* hsrc = (const char*)g_h + ((size_t)(jb + hjr) * DOUT) * 2 + hcb;
            #pragma unroll
            for (int q = 0; q < 4; q++)
                CP_ASYNC16(sHb + sHst + (uint32_t)q * 16u, hsrc + q * 16);
            CP_COMMIT();
            B0r = __ldg((const float4*)(Bp + jb));
            B1r = __ldg((const float4*)(Bp + jb + 4));
            D0r = __ldg((const float4*)(Dp + jb));
            D1r = __ldg((const float4*)(Dp + jb + 4));
            CP_WAIT0();
            #pragma unroll
            for (int k = 0; k < 4; k++) produce_k(k, sPb + sPst);
        }
        __syncthreads();

        for (int cc = c0; cc < c1; ++cc) {
            const int b = (cc - c0) & 1;
            const uint32_t Pcur = sPb + (uint32_t)b * PBUF;
            const uint32_t Hcur = sHb + (uint32_t)b * HBUF;
            const uint32_t Pnxt = sPb + (uint32_t)(b ^ 1) * PBUF;
            const uint32_t Hnxt = sHb + (uint32_t)(b ^ 1) * HBUF;
            const bool more = (cc + 1 < c1);
            const int jbn = ((cc + 1) & 127) * KC;

            if (more) {
                #pragma unroll
                for (int k = 0; k < 4; k++) {
                    const int4* p = (const int4*)(adjbase + (size_t)(32 * k) * NROWS + jbn);
                    adjr[2 * k]     = __ldg(p);
                    adjr[2 * k + 1] = __ldg(p + 1);
                }
                const char* hsrc = (const char*)g_h + ((size_t)(jbn + hjr) * DOUT) * 2 + hcb;
                #pragma unroll
                for (int q = 0; q < 4; q++)
                    CP_ASYNC16(Hnxt + sHst + (uint32_t)q * 16u, hsrc + q * 16);
                CP_COMMIT();
                B0r = __ldg((const float4*)(Bp + jbn));
                B1r = __ldg((const float4*)(Bp + jbn + 4));
                D0r = __ldg((const float4*)(Dp + jbn));
                D1r = __ldg((const float4*)(Dp + jbn + 4));
            }

            #pragma unroll
            for (int ss = 0; ss < 4; ++ss) {
                uint32_t A0[4], A1[4];
                asm volatile("ldmatrix.sync.aligned.m8n8.x4.shared.b16 {%0,%1,%2,%3}, [%4];"
                    : "=r"(A0[0]), "=r"(A0[1]), "=r"(A0[2]), "=r"(A0[3])
                    : "r"(Pcur + (aRow0 + (uint32_t)ss * 16u) * 2u));
                asm volatile("ldmatrix.sync.aligned.m8n8.x4.shared.b16 {%0,%1,%2,%3}, [%4];"
                    : "=r"(A1[0]), "=r"(A1[1]), "=r"(A1[2]), "=r"(A1[3])
                    : "r"(Pcur + (aRow1 + (uint32_t)ss * 16u) * 2u));
                #pragma unroll
                for (int nt = 0; nt < 4; ++nt) {
                    uint32_t b0, b1, b2, b3;
                    asm volatile("ldmatrix.sync.aligned.m8n8.x4.trans.shared.b16 {%0,%1,%2,%3}, [%4];"
                        : "=r"(b0), "=r"(b1), "=r"(b2), "=r"(b3)
                        : "r"(Hcur + (bBase + (uint32_t)ss * 16u * HSTR + (uint32_t)nt * 16u) * 2u));
                    float* d00 = facc[nt * 2];
                    float* d01 = facc[nt * 2 + 1];
                    float* d10 = facc[8 + nt * 2];
                    float* d11 = facc[8 + nt * 2 + 1];
                    asm volatile("mma.sync.aligned.m16n8k16.row.col.f32.f16.f16.f32 "
                        "{%0,%1,%2,%3}, {%4,%5,%6,%7}, {%8,%9}, {%0,%1,%2,%3};"
                        : "+f"(d00[0]), "+f"(d00[1]), "+f"(d00[2]), "+f"(d00[3])
                        : "r"(A0[0]), "r"(A0[1]), "r"(A0[2]), "r"(A0[3]), "r"(b0), "r"(b1));
                    asm volatile("mma.sync.aligned.m16n8k16.row.col.f32.f16.f16.f32 "
                        "{%0,%1,%2,%3}, {%4,%5,%6,%7}, {%8,%9}, {%0,%1,%2,%3};"
                        : "+f"(d01[0]), "+f"(d01[1]), "+f"(d01[2]), "+f"(d01[3])
                        : "r"(A0[0]), "r"(A0[1]), "r"(A0[2]), "r"(A0[3]), "r"(b2), "r"(b3));
                    asm volatile("mma.sync.aligned.m16n8k16.row.col.f32.f16.f16.f32 "
                        "{%0,%1,%2,%3}, {%4,%5,%6,%7}, {%8,%9}, {%0,%1,%2,%3};"
                        : "+f"(d10[0]), "+f"(d10[1]), "+f"(d10[2]), "+f"(d10[3])
                        : "r"(A1[0]), "r"(A1[1]), "r"(A1[2]), "r"(A1[3]), "r"(b0), "r"(b1));
                    asm volatile("mma.sync.aligned.m16n8k16.row.col.f32.f16.f16.f32 "
                        "{%0,%1,%2,%3}, {%4,%5,%6,%7}, {%8,%9}, {%0,%1,%2,%3};"
                        : "+f"(d11[0]), "+f"(d11[1]), "+f"(d11[2]), "+f"(d11[3])
                        : "r"(A1[0]), "r"(A1[1]), "r"(A1[2]), "r"(A1[3]), "r"(b2), "r"(b3));
                }
                if (more) produce_k(ss, Pnxt + sPst);
            }

            CP_WAIT0();
            __syncthreads();
        }

        {
            const int r  = lane >> 2;
            const int c2 = (lane & 3) * 2;
            #pragma unroll
            for (int mt = 0; mt < 2; ++mt) {
                const int row0 = rowb + mwarp * 32 + mt * 16 + r;
                float* dst0 = &g_acc[slot][(size_t)row0 * DOUT];
                float* dst1 = dst0 + (size_t)8 * DOUT;
                #pragma unroll
                for (int nt = 0; nt < 4; ++nt) {
                    #pragma unroll
                    for (int hh = 0; hh < 2; ++hh) {
                        const float* f = facc[mt * 8 + nt * 2 + hh];
                        int col = nwarp * 64 + nt * 16 + hh * 8 + c2;
                        *(float2*)(dst0 + col) = make_float2(f[0], f[1]);
                        *(float2*)(dst1 + col) = make_float2(f[2], f[3]);
                    }
                }
            }
        }
        #pragma unroll
        for (int m = 1; m <= 4; m <<= 1) {
            #pragma unroll
            for (int k = 0; k < 4; k++)
                rsum[k] += __shfl_xor_sync(0xffffffffu, rsum[k], m);
        }
        if (jq8 == 0) {
            #pragma unroll
            for (int k = 0; k < 4; k++)
                g_rs[slot][rowb + tr + 32 * k] = rsum[k];
        }
        __syncthreads();
    }
}

// ============ K3: sum slot partials, normalize ============
__global__ __launch_bounds__(256) void k3_final(float* __restrict__ out)
{
    const int idx = blockIdx.x * 256 + threadIdx.x;
    const int row = idx >> 5;
    float rs = 0.f;
    #pragma unroll
    for (int s2 = 0; s2 < SLOTS; s2++) rs += g_rs[s2][row];
    const float inv = 1.0f / rs;
    float ox = 0.f, oy = 0.f, oz = 0.f, ow = 0.f;
    #pragma unroll
    for (int s2 = 0; s2 < SLOTS; s2++) {
        float4 a = ((const float4*)g_acc[s2])[idx];
        ox += a.x; oy += a.y; oz += a.z; ow += a.w;
    }
    float4 o;
    o.x = ox * inv; o.y = oy * inv; o.z = oz * inv; o.w = ow * inv;
    ((float4*)out)[idx] = o;
}

extern "C" void kernel_launch(void* const* d_in, const int* in_sizes, int n_in,
                              void* d_out, int out_size) {
    const float* x   = (const float*)d_in[0];
    const int*   adj = (const int*)  d_in[1];
    const float* W   = (const float*)d_in[2];
    const float* bW  = (const float*)d_in[3];
    const float* a1  = (const float*)d_in[4];
    const float* a2  = (const float*)d_in[5];
    const float* ba  = (const float*)d_in[6];
    float* out = (float*)d_out;

    static bool attr_set = false;
    if (!attr_set) {
        cudaFuncSetAttribute(k2_fused, cudaFuncAttributeMaxDynamicSharedMemorySize, SMEM_K2);
        cudaFuncSetAttribute(k1_mma, cudaFuncAttributeMaxDynamicSharedMemorySize, SMEM_K1);
        attr_set = true;
    }

    k0_split<<<1040, 256>>>(x, W);
    k1_mma<<<NROWS / 32, 256, SMEM_K1>>>(bW, a1, a2, ba);
    k2_fused<<<NCTA, 256, SMEM_K2>>>(adj);
    k3_final<<<(NROWS * DOUT / 4) / 256, 256>>>(out);
}

// round 13
// speedup vs baseline: 1.1880x; 1.0278x over previous
#include <cuda_runtime.h>
#include <cuda_fp16.h>
#include <cstdint>

#define NROWS 8192
#define DIN   256
#define DOUT  128
#define KC    64
#define TILE_M 128
#define NCTA  296
#define SLOTS 6

// ---- device-global scratch (no allocations allowed; zero-initialized) ----
__device__ __half g_h[(size_t)NROWS * DOUT];   // h fp16 row-major
__device__ __half g_Wh[(size_t)DIN * DOUT];
__device__ __half g_Wl[(size_t)DIN * DOUT];
__device__ float  g_B[NROWS];
__device__ float  g_D[NROWS];
__device__ float  g_E[NROWS];
__device__ float  g_acc[SLOTS][(size_t)NROWS * DOUT];  // slot partials (zero-init)
__device__ float  g_rs[SLOTS][NROWS];                  // rowsum partials (zero-init)

__device__ __forceinline__ uint32_t smem_u32(const void* p) {
    uint32_t a;
    asm("{ .reg .u64 t; cvta.to.shared.u64 t, %1; cvt.u32.u64 %0, t; }" : "=r"(a) : "l"(p));
    return a;
}

// streaming (evict-first) 16B global load — for one-pass adj data
__device__ __forceinline__ int4 ldg_cs(const int4* p) {
    int4 v;
    asm("ld.global.cs.v4.u32 {%0,%1,%2,%3}, [%4];"
        : "=r"(v.x), "=r"(v.y), "=r"(v.z), "=r"(v.w) : "l"(p));
    return v;
}

#define CP_ASYNC16(dst, src) \
    asm volatile("cp.async.cg.shared.global [%0], [%1], 16;" :: "r"(dst), "l"(src) : "memory")
#define CP_COMMIT() asm volatile("cp.async.commit_group;" ::: "memory")
#define CP_WAIT0()  asm volatile("cp.async.wait_group 0;" ::: "memory")

// ============ K0: split W into fp16 hi/lo (W only; x handled in k1) ============
__global__ __launch_bounds__(256) void k0_splitW(const float* __restrict__ W)
{
    size_t e = ((size_t)blockIdx.x * 256 + threadIdx.x) * 8;   // 16 CTAs x 2048 = 32768
    float4 v0 = __ldg((const float4*)(W + e));
    float4 v1 = __ldg((const float4*)(W + e + 4));
    __half hi[8], lo[8];
    const float* v = (const float*)&v0;
    #pragma unroll
    for (int i = 0; i < 4; i++) {
        hi[i] = __float2half_rn(v[i]);
        lo[i] = __float2half_rn(v[i] - __half2float(hi[i]));
    }
    v = (const float*)&v1;
    #pragma unroll
    for (int i = 0; i < 4; i++) {
        hi[4 + i] = __float2half_rn(v[i]);
        lo[4 + i] = __float2half_rn(v[i] - __half2float(hi[4 + i]));
    }
    *(uint4*)(g_Wh + e) = *(const uint4*)hi;
    *(uint4*)(g_Wl + e) = *(const uint4*)lo;
}

// ============ K1: h = xW + b via split-fp16 HMMA (x split fused), plus B/D/E ============
// 256 CTAs x 256 thr, 32 rows/CTA, K=256 in 4 chunks of 64, double-buffered.
// Per buffer: fp32 x stage [32x68f], Ah/Al [32x72h], Bh/Bl [64x136h].
#define K1ASTR 72u
#define K1BSTR 136u
#define K1XSTR 68u
#define K1_XS  0u
#define K1_AH  8704u
#define K1_AL  13312u
#define K1_BH  17920u
#define K1_BL  35328u
#define K1BUF  52736u
#define SMEM_K1 (2 * 52736)

__global__ __launch_bounds__(256, 2) void k1_mma(
    const float* __restrict__ x,
    const float* __restrict__ bW, const float* __restrict__ a1,
    const float* __restrict__ a2, const float* __restrict__ ba_p)
{
    extern __shared__ char smem[];
    const uint32_t sb = smem_u32(smem);
    __shared__ float red1[32][4];
    __shared__ float red2[32][4];

    const int tid  = threadIdx.x;
    const int wid  = tid >> 5;
    const int lane = tid & 31;
    const int rb   = blockIdx.x * 32;
    const int mwarp = wid & 1;
    const int nwarp = wid >> 1;

    // ldmatrix addressing
    const int g  = lane >> 3;
    const int l7 = lane & 7;
    const uint32_t aOff = (uint32_t)(mwarp * 16 + (g & 1) * 8 + l7) * K1ASTR + (uint32_t)((g >> 1) * 8);
    const uint32_t bOff = (uint32_t)((g & 1) * 8 + l7) * K1BSTR + (uint32_t)((g >> 1) * 8) + (uint32_t)nwarp * 32u;

    // convert mapping: row = tid>>3, 8 cols at (tid&7)*8
    const int crow = tid >> 3;
    const int cc8  = (tid & 7) * 8;

    float facc[4][4];
    #pragma unroll
    for (int n = 0; n < 4; n++)
        #pragma unroll
        for (int c = 0; c < 4; c++) facc[n][c] = 0.f;

    auto stage = [&](int buf, int chunk) {
        const uint32_t base = sb + (uint32_t)buf * K1BUF;
        const int kc = chunk * 64;
        // x fp32: 512 pieces of 16B, 2 per thread
        #pragma unroll
        for (int i = 0; i < 2; i++) {
            int pe = tid + 256 * i;
            int r = pe >> 4, p = pe & 15;
            CP_ASYNC16(base + K1_XS + (uint32_t)r * (K1XSTR * 4u) + (uint32_t)p * 16u,
                       x + (size_t)(rb + r) * DIN + kc + p * 4);
        }
        // W tiles: 4 pieces each array
        #pragma unroll
        for (int i = 0; i < 4; i++) {
            int e2 = tid + 256 * i;
            int k = e2 >> 4, p = e2 & 15;
            uint32_t d = (uint32_t)k * (K1BSTR * 2u) + (uint32_t)p * 16u;
            CP_ASYNC16(base + K1_BH + d, g_Wh + (size_t)(kc + k) * DOUT + p * 8);
            CP_ASYNC16(base + K1_BL + d, g_Wl + (size_t)(kc + k) * DOUT + p * 8);
        }
        CP_COMMIT();
    };

    stage(0, 0);
    for (int cc = 0; cc < 4; ++cc) {
        const int buf = cc & 1;
        const uint32_t base = sb + (uint32_t)buf * K1BUF;
        CP_WAIT0();
        __syncthreads();

        // ---- convert staged fp32 x -> Ah/Al fp16 smem ----
        {
            float v[8];
            uint32_t xaddr = base + K1_XS + (uint32_t)crow * (K1XSTR * 4u) + (uint32_t)cc8 * 4u;
            asm("ld.shared.v4.f32 {%0,%1,%2,%3}, [%4];"
                : "=f"(v[0]), "=f"(v[1]), "=f"(v[2]), "=f"(v[3]) : "r"(xaddr));
            asm("ld.shared.v4.f32 {%0,%1,%2,%3}, [%4];"
                : "=f"(v[4]), "=f"(v[5]), "=f"(v[6]), "=f"(v[7]) : "r"(xaddr + 16u));
            __half hi[8], lo[8];
            #pragma unroll
            for (int i = 0; i < 8; i++) {
                hi[i] = __float2half_rn(v[i]);
                lo[i] = __float2half_rn(v[i] - __half2float(hi[i]));
            }
            uint32_t hdst = base + K1_AH + ((uint32_t)crow * K1ASTR + (uint32_t)cc8) * 2u;
            uint32_t ldst = base + K1_AL + ((uint32_t)crow * K1ASTR + (uint32_t)cc8) * 2u;
            const uint32_t* hw = (const uint32_t*)hi;
            const uint32_t* lw = (const uint32_t*)lo;
            asm volatile("st.shared.v4.b32 [%0], {%1,%2,%3,%4};"
                :: "r"(hdst), "r"(hw[0]), "r"(hw[1]), "r"(hw[2]), "r"(hw[3]) : "memory");
            asm volatile("st.shared.v4.b32 [%0], {%1,%2,%3,%4};"
                :: "r"(ldst), "r"(lw[0]), "r"(lw[1]), "r"(lw[2]), "r"(lw[3]) : "memory");
        }
        __syncthreads();

        if (cc < 3) stage(buf ^ 1, cc + 1);   // overlap next loads with MMA

        #pragma unroll
        for (int ss = 0; ss < 4; ++ss) {
            uint32_t Ah[4], Al[4];
            asm volatile("ldmatrix.sync.aligned.m8n8.x4.shared.b16 {%0,%1,%2,%3}, [%4];"
                : "=r"(Ah[0]), "=r"(Ah[1]), "=r"(Ah[2]), "=r"(Ah[3])
                : "r"(base + K1_AH + (aOff + (uint32_t)ss * 16u) * 2u));
            asm volatile("ldmatrix.sync.aligned.m8n8.x4.shared.b16 {%0,%1,%2,%3}, [%4];"
                : "=r"(Al[0]), "=r"(Al[1]), "=r"(Al[2]), "=r"(Al[3])
                : "r"(base + K1_AL + (aOff + (uint32_t)ss * 16u) * 2u));
            #pragma unroll
            for (int ntg = 0; ntg < 2; ++ntg) {
                uint32_t bh0, bh1, bh2, bh3, bl0, bl1, bl2, bl3;
                uint32_t baddr = (bOff + (uint32_t)ss * 16u * K1BSTR + (uint32_t)ntg * 16u) * 2u;
                asm volatile("ldmatrix.sync.aligned.m8n8.x4.trans.shared.b16 {%0,%1,%2,%3}, [%4];"
                    : "=r"(bh0), "=r"(bh1), "=r"(bh2), "=r"(bh3) : "r"(base + K1_BH + baddr));
                asm volatile("ldmatrix.sync.aligned.m8n8.x4.trans.shared.b16 {%0,%1,%2,%3}, [%4];"
                    : "=r"(bl0), "=r"(bl1), "=r"(bl2), "=r"(bl3) : "r"(base + K1_BL + baddr));
                float* d0 = facc[ntg * 2];
                float* d1 = facc[ntg * 2 + 1];
                asm volatile("mma.sync.aligned.m16n8k16.row.col.f32.f16.f16.f32 "
                    "{%0,%1,%2,%3}, {%4,%5,%6,%7}, {%8,%9}, {%0,%1,%2,%3};"
                    : "+f"(d0[0]), "+f"(d0[1]), "+f"(d0[2]), "+f"(d0[3])
                    : "r"(Ah[0]), "r"(Ah[1]), "r"(Ah[2]), "r"(Ah[3]), "r"(bh0), "r"(bh1));
                asm volatile("mma.sync.aligned.m16n8k16.row.col.f32.f16.f16.f32 "
                    "{%0,%1,%2,%3}, {%4,%5,%6,%7}, {%8,%9}, {%0,%1,%2,%3};"
                    : "+f"(d1[0]), "+f"(d1[1]), "+f"(d1[2]), "+f"(d1[3])
                    : "r"(Ah[0]), "r"(Ah[1]), "r"(Ah[2]), "r"(Ah[3]), "r"(bh2), "r"(bh3));
                asm volatile("mma.sync.aligned.m16n8k16.row.col.f32.f16.f16.f32 "
                    "{%0,%1,%2,%3}, {%4,%5,%6,%7}, {%8,%9}, {%0,%1,%2,%3};"
                    : "+f"(d0[0]), "+f"(d0[1]), "+f"(d0[2]), "+f"(d0[3])
                    : "r"(Ah[0]), "r"(Ah[1]), "r"(Ah[2]), "r"(Ah[3]), "r"(bl0), "r"(bl1));
                asm volatile("mma.sync.aligned.m16n8k16.row.col.f32.f16.f16.f32 "
                    "{%0,%1,%2,%3}, {%4,%5,%6,%7}, {%8,%9}, {%0,%1,%2,%3};"
                    : "+f"(d1[0]), "+f"(d1[1]), "+f"(d1[2]), "+f"(d1[3])
                    : "r"(Ah[0]), "r"(Ah[1]), "r"(Ah[2]), "r"(Ah[3]), "r"(bl2), "r"(bl3));
                asm volatile("mma.sync.aligned.m16n8k16.row.col.f32.f16.f16.f32 "
                    "{%0,%1,%2,%3}, {%4,%5,%6,%7}, {%8,%9}, {%0,%1,%2,%3};"
                    : "+f"(d0[0]), "+f"(d0[1]), "+f"(d0[2]), "+f"(d0[3])
                    : "r"(Al[0]), "r"(Al[1]), "r"(Al[2]), "r"(Al[3]), "r"(bh0), "r"(bh1));
                asm volatile("mma.sync.aligned.m16n8k16.row.col.f32.f16.f16.f32 "
                    "{%0,%1,%2,%3}, {%4,%5,%6,%7}, {%8,%9}, {%0,%1,%2,%3};"
                    : "+f"(d1[0]), "+f"(d1[1]), "+f"(d1[2]), "+f"(d1[3])
                    : "r"(Al[0]), "r"(Al[1]), "r"(Al[2]), "r"(Al[3]), "r"(bh2), "r"(bh3));
            }
        }
        __syncthreads();   // MMA reads done before this buf is restaged
    }

    // ---- epilogue: bias, h write, s1/s2, E/B/D ----
    const int r  = lane >> 2;
    const int c2 = (lane & 3) * 2;
    const int row0 = mwarp * 16 + r;
    float s1a = 0.f, s2a = 0.f, s1b = 0.f, s2b = 0.f;

    #pragma unroll
    for (int nt = 0; nt < 4; ++nt) {
        const int col = nwarp * 32 + nt * 8 + c2;
        float2 bv = *(const float2*)&bW[col];
        float2 a1v = *(const float2*)&a1[col];
        float2 a2v = *(const float2*)&a2[col];
        float h00 = facc[nt][0] + bv.x, h01 = facc[nt][1] + bv.y;
        float h10 = facc[nt][2] + bv.x, h11 = facc[nt][3] + bv.y;
        __half2 p0 = __floats2half2_rn(h00, h01);
        __half2 p1 = __floats2half2_rn(h10, h11);
        *(uint32_t*)(g_h + (size_t)(rb + row0) * DOUT + col)     = *(const uint32_t*)&p0;
        *(uint32_t*)(g_h + (size_t)(rb + row0 + 8) * DOUT + col) = *(const uint32_t*)&p1;
        s1a += h00 * a1v.x + h01 * a1v.y;
        s2a += h00 * a2v.x + h01 * a2v.y;
        s1b += h10 * a1v.x + h11 * a1v.y;
        s2b += h10 * a2v.x + h11 * a2v.y;
    }
    #pragma unroll
    for (int m = 1; m <= 2; m <<= 1) {
        s1a += __shfl_xor_sync(0xffffffffu, s1a, m);
        s2a += __shfl_xor_sync(0xffffffffu, s2a, m);
        s1b += __shfl_xor_sync(0xffffffffu, s1b, m);
        s2b += __shfl_xor_sync(0xffffffffu, s2b, m);
    }
    if ((lane & 3) == 0) {
        red1[row0][nwarp] = s1a;  red2[row0][nwarp] = s2a;
        red1[row0 + 8][nwarp] = s1b;  red2[row0 + 8][nwarp] = s2b;
    }
    __syncthreads();
    if (tid < 32) {
        float s1 = red1[tid][0] + red1[tid][1] + red1[tid][2] + red1[tid][3];
        float s2 = red2[tid][0] + red2[tid][1] + red2[tid][2] + red2[tid][3];
        float u = s1 + ba_p[0];
        g_E[rb + tid] = expf(-0.99f * u);
        g_B[rb + tid] = expf(s2);
        g_D[rb + tid] = expf(0.01f * s2);
    }
}

// ============ K2: fused masked-softmax-numerator GEMM (R11 + streaming adj) ============
#define PSTR 72u
#define HSTR 136u
#define PBUF (128u * PSTR * 2u)
#define HBUF (64u * HSTR * 2u)
#define SMEM_K2 (2 * 18432 + 2 * 17408)

__global__ __launch_bounds__(256, 2) void k2_fused(const int* __restrict__ adj)
{
    extern __shared__ char smem[];
    const uint32_t sPb = smem_u32(smem);
    const uint32_t sHb = sPb + 2u * PBUF;

    const int tid  = threadIdx.x;
    const int wid  = tid >> 5;
    const int lane = tid & 31;
    const int cta  = blockIdx.x;
    const int slot = cta % SLOTS;

    const int s = (1024 * cta) / 37;
    const int e = (1024 * (cta + 1)) / 37;

    const int tr  = tid >> 3;
    const int jq8 = tid & 7;
    const int hjr = tid >> 2;
    const int hcb = (tid & 3) * 64;

    const int mwarp = wid & 3;
    const int nwarp = wid >> 2;
    const uint32_t ncol0 = (uint32_t)nwarp * 64u;

    const int g  = lane >> 3;
    const int l7 = lane & 7;
    const uint32_t aRow0 = (uint32_t)(mwarp * 32 + (g & 1) * 8 + l7) * PSTR + (uint32_t)((g >> 1) * 8);
    const uint32_t aRow1 = aRow0 + 16u * PSTR;
    const uint32_t bBase = (uint32_t)((g & 1) * 8 + l7) * HSTR + (uint32_t)((g >> 1) * 8) + ncol0;

    const uint32_t sPst = ((uint32_t)tr * PSTR + (uint32_t)jq8 * 8u) * 2u;
    const uint32_t sHst = (uint32_t)hjr * HSTR * 2u + (uint32_t)hcb;

    const float* Bp = g_B + jq8 * 8;
    const float* Dp = g_D + jq8 * 8;

    const int t0 = s >> 7, t1 = (e - 1) >> 7;
    for (int t = t0; t <= t1; ++t) {
        const int c0 = (s > (t << 7)) ? s : (t << 7);
        const int c1 = (e < ((t + 1) << 7)) ? e : ((t + 1) << 7);
        const int rowb = t * TILE_M;

        float Ei[4];
        #pragma unroll
        for (int k = 0; k < 4; k++) Ei[k] = g_E[rowb + tr + 32 * k];

        const int* adjbase = adj + (size_t)(rowb + tr) * NROWS + jq8 * 8;

        float facc[16][4];
        #pragma unroll
        for (int n = 0; n < 16; n++)
            #pragma unroll
            for (int c = 0; c < 4; c++) facc[n][c] = 0.f;
        float rsum[4] = {0.f, 0.f, 0.f, 0.f};

        int4 adjr[8];
        float4 B0r, B1r, D0r, D1r;

        auto produce_k = [&](int k, uint32_t stb) {
            int4 a0 = adjr[2 * k], a1 = adjr[2 * k + 1];
            float v0 = fmaxf(B0r.x, Ei[k] * D0r.x); v0 = a0.x ? v0 : 0.f;
            float v1 = fmaxf(B0r.y, Ei[k] * D0r.y); v1 = a0.y ? v1 : 0.f;
            float v2 = fmaxf(B0r.z, Ei[k] * D0r.z); v2 = a0.z ? v2 : 0.f;
            float v3 = fmaxf(B0r.w, Ei[k] * D0r.w); v3 = a0.w ? v3 : 0.f;
            float v4 = fmaxf(B1r.x, Ei[k] * D1r.x); v4 = a1.x ? v4 : 0.f;
            float v5 = fmaxf(B1r.y, Ei[k] * D1r.y); v5 = a1.y ? v5 : 0.f;
            float v6 = fmaxf(B1r.z, Ei[k] * D1r.z); v6 = a1.z ? v6 : 0.f;
            float v7 = fmaxf(B1r.w, Ei[k] * D1r.w); v7 = a1.w ? v7 : 0.f;
            rsum[k] += ((v0 + v1) + (v2 + v3)) + ((v4 + v5) + (v6 + v7));
            __half2 p0 = __floats2half2_rn(v0, v1);
            __half2 p1 = __floats2half2_rn(v2, v3);
            __half2 p2 = __floats2half2_rn(v4, v5);
            __half2 p3 = __floats2half2_rn(v6, v7);
            asm volatile("st.shared.v4.b32 [%0], {%1,%2,%3,%4};"
                :: "r"(stb + (uint32_t)(32 * k) * PSTR * 2u),
                   "r"(*(const uint32_t*)&p0), "r"(*(const uint32_t*)&p1),
                   "r"(*(const uint32_t*)&p2), "r"(*(const uint32_t*)&p3) : "memory");
        };

        {
            const int jb = (c0 & 127) * KC;
            #pragma unroll
            for (int k = 0; k < 4; k++) {
                const int4* p = (const int4*)(adjbase + (size_t)(32 * k) * NROWS + jb);
                adjr[2 * k]     = ldg_cs(p);
                adjr[2 * k + 1] = ldg_cs(p + 1);
            }
            const char* hsrc = (const char*)g_h + ((size_t)(jb + hjr) * DOUT) * 2 + hcb;
            #pragma unroll
            for (int q = 0; q < 4; q++)
                CP_ASYNC16(sHb + sHst + (uint32_t)q * 16u, hsrc + q * 16);
            CP_COMMIT();
            B0r = __ldg((const float4*)(Bp + jb));
            B1r = __ldg((const float4*)(Bp + jb + 4));
            D0r = __ldg((const float4*)(Dp + jb));
            D1r = __ldg((const float4*)(Dp + jb + 4));
            CP_WAIT0();
            #pragma unroll
            for (int k = 0; k < 4; k++) produce_k(k, sPb + sPst);
        }
        __syncthreads();

        for (int cc = c0; cc < c1; ++cc) {
            const int b = (cc - c0) & 1;
            const uint32_t Pcur = sPb + (uint32_t)b * PBUF;
            const uint32_t Hcur = sHb + (uint32_t)b * HBUF;
            const uint32_t Pnxt = sPb + (uint32_t)(b ^ 1) * PBUF;
            const uint32_t Hnxt = sHb + (uint32_t)(b ^ 1) * HBUF;
            const bool more = (cc + 1 < c1);
            const int jbn = ((cc + 1) & 127) * KC;

            if (more) {
                #pragma unroll
                for (int k = 0; k < 4; k++) {
                    const int4* p = (const int4*)(adjbase + (size_t)(32 * k) * NROWS + jbn);
                    adjr[2 * k]     = ldg_cs(p);
                    adjr[2 * k + 1] = ldg_cs(p + 1);
                }
                const char* hsrc = (const char*)g_h + ((size_t)(jbn + hjr) * DOUT) * 2 + hcb;
                #pragma unroll
                for (int q = 0; q < 4; q++)
                    CP_ASYNC16(Hnxt + sHst + (uint32_t)q * 16u, hsrc + q * 16);
                CP_COMMIT();
                B0r = __ldg((const float4*)(Bp + jbn));
                B1r = __ldg((const float4*)(Bp + jbn + 4));
                D0r = __ldg((const float4*)(Dp + jbn));
                D1r = __ldg((const float4*)(Dp + jbn + 4));
            }

            #pragma unroll
            for (int ss = 0; ss < 4; ++ss) {
                uint32_t A0[4], A1[4];
                asm volatile("ldmatrix.sync.aligned.m8n8.x4.shared.b16 {%0,%1,%2,%3}, [%4];"
                    : "=r"(A0[0]), "=r"(A0[1]), "=r"(A0[2]), "=r"(A0[3])
                    : "r"(Pcur + (aRow0 + (uint32_t)ss * 16u) * 2u));
                asm volatile("ldmatrix.sync.aligned.m8n8.x4.shared.b16 {%0,%1,%2,%3}, [%4];"
                    : "=r"(A1[0]), "=r"(A1[1]), "=r"(A1[2]), "=r"(A1[3])
                    : "r"(Pcur + (aRow1 + (uint32_t)ss * 16u) * 2u));
                #pragma unroll
                for (int nt = 0; nt < 4; ++nt) {
                    uint32_t b0, b1, b2, b3;
                    asm volatile("ldmatrix.sync.aligned.m8n8.x4.trans.shared.b16 {%0,%1,%2,%3}, [%4];"
                        : "=r"(b0), "=r"(b1), "=r"(b2), "=r"(b3)
                        : "r"(Hcur + (bBase + (uint32_t)ss * 16u * HSTR + (uint32_t)nt * 16u) * 2u));
                    float* d00 = facc[nt * 2];
                    float* d01 = facc[nt * 2 + 1];
                    float* d10 = facc[8 + nt * 2];
                    float* d11 = facc[8 + nt * 2 + 1];
                    asm volatile("mma.sync.aligned.m16n8k16.row.col.f32.f16.f16.f32 "
                        "{%0,%1,%2,%3}, {%4,%5,%6,%7}, {%8,%9}, {%0,%1,%2,%3};"
                        : "+f"(d00[0]), "+f"(d00[1]), "+f"(d00[2]), "+f"(d00[3])
                        : "r"(A0[0]), "r"(A0[1]), "r"(A0[2]), "r"(A0[3]), "r"(b0), "r"(b1));
                    asm volatile("mma.sync.aligned.m16n8k16.row.col.f32.f16.f16.f32 "
                        "{%0,%1,%2,%3}, {%4,%5,%6,%7}, {%8,%9}, {%0,%1,%2,%3};"
                        : "+f"(d01[0]), "+f"(d01[1]), "+f"(d01[2]), "+f"(d01[3])
                        : "r"(A0[0]), "r"(A0[1]), "r"(A0[2]), "r"(A0[3]), "r"(b2), "r"(b3));
                    asm volatile("mma.sync.aligned.m16n8k16.row.col.f32.f16.f16.f32 "
                        "{%0,%1,%2,%3}, {%4,%5,%6,%7}, {%8,%9}, {%0,%1,%2,%3};"
                        : "+f"(d10[0]), "+f"(d10[1]), "+f"(d10[2]), "+f"(d10[3])
                        : "r"(A1[0]), "r"(A1[1]), "r"(A1[2]), "r"(A1[3]), "r"(b0), "r"(b1));
                    asm volatile("mma.sync.aligned.m16n8k16.row.col.f32.f16.f16.f32 "
                        "{%0,%1,%2,%3}, {%4,%5,%6,%7}, {%8,%9}, {%0,%1,%2,%3};"
                        : "+f"(d11[0]), "+f"(d11[1]), "+f"(d11[2]), "+f"(d11[3])
                        : "r"(A1[0]), "r"(A1[1]), "r"(A1[2]), "r"(A1[3]), "r"(b2), "r"(b3));
                }
                if (more) produce_k(ss, Pnxt + sPst);
            }

            CP_WAIT0();
            __syncthreads();
        }

        {
            const int r  = lane >> 2;
            const int c2 = (lane & 3) * 2;
            #pragma unroll
            for (int mt = 0; mt < 2; ++mt) {
                const int row0 = rowb + mwarp * 32 + mt * 16 + r;
                float* dst0 = &g_acc[slot][(size_t)row0 * DOUT];
                float* dst1 = dst0 + (size_t)8 * DOUT;
                #pragma unroll
                for (int nt = 0; nt < 4; ++nt) {
                    #pragma unroll
                    for (int hh = 0; hh < 2; ++hh) {
                        const float* f = facc[mt * 8 + nt * 2 + hh];
                        int col = nwarp * 64 + nt * 16 + hh * 8 + c2;
                        *(float2*)(dst0 + col) = make_float2(f[0], f[1]);
                        *(float2*)(dst1 + col) = make_float2(f[2], f[3]);
                    }
                }
            }
        }
        #pragma unroll
        for (int m = 1; m <= 4; m <<= 1) {
            #pragma unroll
            for (int k = 0; k < 4; k++)
                rsum[k] += __shfl_xor_sync(0xffffffffu, rsum[k], m);
        }
        if (jq8 == 0) {
            #pragma unroll
            for (int k = 0; k < 4; k++)
                g_rs[slot][rowb + tr + 32 * k] = rsum[k];
        }
        __syncthreads();
    }
}

// ============ K3: sum slot partials, normalize ============
__global__ __launch_bounds__(256) void k3_final(float* __restrict__ out)
{
    const int idx = blockIdx.x * 256 + threadIdx.x;
    const int row = idx >> 5;
    float rs = 0.f;
    #pragma unroll
    for (int s2 = 0; s2 < SLOTS; s2++) rs += g_rs[s2][row];
    const float inv = 1.0f / rs;
    float ox = 0.f, oy = 0.f, oz = 0.f, ow = 0.f;
    #pragma unroll
    for (int s2 = 0; s2 < SLOTS; s2++) {
        float4 a = ((const float4*)g_acc[s2])[idx];
        ox += a.x; oy += a.y; oz += a.z; ow += a.w;
    }
    float4 o;
    o.x = ox * inv; o.y = oy * inv; o.z = oz * inv; o.w = ow * inv;
    ((float4*)out)[idx] = o;
}

extern "C" void kernel_launch(void* const* d_in, const int* in_sizes, int n_in,
                              void* d_out, int out_size) {
    const float* x   = (const float*)d_in[0];
    const int*   adj = (const int*)  d_in[1];
    const float* W   = (const float*)d_in[2];
    const float* bW  = (const float*)d_in[3];
    const float* a1  = (const float*)d_in[4];
    const float* a2  = (const float*)d_in[5];
    const float* ba  = (const float*)d_in[6];
    float* out = (float*)d_out;

    static bool attr_set = false;
    if (!attr_set) {
        cudaFuncSetAttribute(k2_fused, cudaFuncAttributeMaxDynamicSharedMemorySize, SMEM_K2);
        cudaFuncSetAttribute(k1_mma, cudaFuncAttributeMaxDynamicSharedMemorySize, SMEM_K1);
        attr_set = true;
    }

    k0_splitW<<<16, 256>>>(W);
    k1_mma<<<NROWS / 32, 256, SMEM_K1>>>(x, bW, a1, a2, ba);
    k2_fused<<<NCTA, 256, SMEM_K2>>>(adj);
    k3_final<<<(NROWS * DOUT / 4) / 256, 256>>>(out);
}